// round 4
// baseline (speedup 1.0000x reference)
#include <cuda_runtime.h>
#include <cuda_bf16.h>

// Problem constants
#define Bq   4
#define Sq   1023           // word sequence length (queries)
#define SK   1024           // keys = image(1) + words(1023)
#define EMB  1024
#define NH   16
#define HD   64
#define MTOT (Bq*Sq)        // 4092 rows for the dense GEMMs

// -------- scratch (device globals; no runtime allocation allowed) --------
__device__ float g_Q [Bq*NH*Sq*HD];   // [b][h][s][d]
__device__ float g_K [Bq*NH*SK*HD];   // [b][h][k][d], k=0 is image key
__device__ float g_V [Bq*NH*SK*HD];
__device__ float g_AO[Bq*Sq*EMB];     // attention output, (b,s,e) layout

// =====================================================================
// Kernel 1: qkv GEMM  C = word(4092x1024) @ c_attn_w(1024x3072) + bias,
//           scatter epilogue into g_Q/g_K/g_V (head-major).
// 128x128 tile, BK=8, 8x8 per thread, 256 threads.
// =====================================================================
#define BM 128
#define BN 128
#define BKK 8

__global__ __launch_bounds__(256, 2)
void qkv_gemm_kernel(const float* __restrict__ A,
                     const float* __restrict__ W,
                     const float* __restrict__ bias)
{
    __shared__ float As[BKK][BM];
    __shared__ float Bs[BKK][BN];

    const int tid = threadIdx.x;
    const int tx  = tid & 15;        // 0..15  (N direction)
    const int ty  = tid >> 4;        // 0..15  (M direction)
    const int bm  = blockIdx.y * BM;
    const int bn  = blockIdx.x * BN;

    const int a_m = tid >> 1;           // 0..127
    const int a_k = (tid & 1) * 4;      // 0 or 4
    const int b_k = tid >> 5;           // 0..7
    const int b_n = (tid & 31) * 4;     // 0..124

    float acc[8][8];
    #pragma unroll
    for (int i = 0; i < 8; i++)
        #pragma unroll
        for (int j = 0; j < 8; j++) acc[i][j] = 0.0f;

    const int Ktot = EMB, Ntot = 3 * EMB;

    for (int k0 = 0; k0 < Ktot; k0 += BKK) {
        float4 av = make_float4(0.f, 0.f, 0.f, 0.f);
        const int gm = bm + a_m;
        if (gm < MTOT) av = *(const float4*)&A[(size_t)gm * Ktot + k0 + a_k];
        As[a_k + 0][a_m] = av.x;
        As[a_k + 1][a_m] = av.y;
        As[a_k + 2][a_m] = av.z;
        As[a_k + 3][a_m] = av.w;

        float4 bv = *(const float4*)&W[(size_t)(k0 + b_k) * Ntot + bn + b_n];
        *(float4*)&Bs[b_k][b_n] = bv;
        __syncthreads();

        #pragma unroll
        for (int kk = 0; kk < BKK; kk++) {
            float a[8], b[8];
            *(float4*)&a[0] = *(const float4*)&As[kk][ty * 8];
            *(float4*)&a[4] = *(const float4*)&As[kk][ty * 8 + 4];
            *(float4*)&b[0] = *(const float4*)&Bs[kk][tx * 8];
            *(float4*)&b[4] = *(const float4*)&Bs[kk][tx * 8 + 4];
            #pragma unroll
            for (int i = 0; i < 8; i++)
                #pragma unroll
                for (int j = 0; j < 8; j++)
                    acc[i][j] = fmaf(a[i], b[j], acc[i][j]);
        }
        __syncthreads();
    }

    // scatter epilogue: n<1024 -> Q, <2048 -> K (slot s+1), else V (slot s+1)
    #pragma unroll
    for (int i = 0; i < 8; i++) {
        const int m = bm + ty * 8 + i;
        if (m >= MTOT) continue;
        const int b_ = m / Sq;
        const int s  = m - b_ * Sq;
        #pragma unroll
        for (int j = 0; j < 8; j++) {
            const int n = bn + tx * 8 + j;
            const float v = acc[i][j] + bias[n];
            const int sec = n >> 10;
            const int e   = n & 1023;
            const int h   = e >> 6;
            const int d   = e & 63;
            if (sec == 0)
                g_Q[(((size_t)(b_ * NH + h)) * Sq + s) * HD + d] = v;
            else if (sec == 1)
                g_K[(((size_t)(b_ * NH + h)) * SK + (s + 1)) * HD + d] = v;
            else
                g_V[(((size_t)(b_ * NH + h)) * SK + (s + 1)) * HD + d] = v;
        }
    }
}

// =====================================================================
// Kernel 2: image k/v.  k_img[b][e] = sum_f img[b][f]*uk_w[e][f] + uk_b[e]
// One warp per output element (8192 outputs). Writes key slot 0.
// =====================================================================
__global__ __launch_bounds__(256)
void imgkv_kernel(const float* __restrict__ img,
                  const float* __restrict__ ukw, const float* __restrict__ ukb,
                  const float* __restrict__ uvw, const float* __restrict__ uvb)
{
    const int warp = threadIdx.x >> 5;
    const int lane = threadIdx.x & 31;
    const int idx  = blockIdx.x * 8 + warp;       // 0..8191
    const int kv   = idx >> 12;                    // 0 = K, 1 = V
    const int rem  = idx & 4095;
    const int b    = rem >> 10;
    const int e    = rem & 1023;

    const float* w = (kv == 0 ? ukw : uvw) + (size_t)e * EMB;
    const float* x = img + (size_t)b * EMB;

    float s = 0.0f;
    #pragma unroll
    for (int t = 0; t < 8; t++) {
        const int f = (lane + t * 32) * 4;
        float4 wv = *(const float4*)&w[f];
        float4 xv = *(const float4*)&x[f];
        s = fmaf(wv.x, xv.x, s);
        s = fmaf(wv.y, xv.y, s);
        s = fmaf(wv.z, xv.z, s);
        s = fmaf(wv.w, xv.w, s);
    }
    #pragma unroll
    for (int off = 16; off >= 1; off >>= 1)
        s += __shfl_xor_sync(0xffffffffu, s, off, 32);

    if (lane == 0) {
        const float bv = (kv == 0 ? ukb : uvb)[e];
        const int h = e >> 6, d = e & 63;
        float* dst = (kv == 0 ? g_K : g_V);
        dst[(((size_t)(b * NH + h)) * SK + 0) * HD + d] = s + bv;
    }
}

// =====================================================================
// Kernel 3: flash attention, fp32.
// Block = 256 threads (16x16). 64-query tile, stream 64-key tiles.
// smem: Qs[d][q], Ks[d][k] (reused as P[q][k]), Vs[k][d]; stride 68.
// Causal: key j visible to query i iff j <= i+1 (key 0 = image, always).
// =====================================================================
#define STRD 68
#define ATTN_SMEM (3 * 64 * STRD * 4)

__global__ __launch_bounds__(256)
void attn_kernel(const float* __restrict__ am)
{
    extern __shared__ float sm[];
    float* Qs = sm;                 // [64][STRD], d-major: Qs[d*STRD + q]
    float* Ks = sm + 64 * STRD;     // [64][STRD], d-major; reused as P[q*STRD+k]
    float* Vs = sm + 2 * 64 * STRD; // [64][STRD], k-major: Vs[k*STRD + d]

    const int b  = blockIdx.z;
    const int h  = blockIdx.y;
    const int qt = blockIdx.x;
    const int tid = threadIdx.x;
    const int tx = tid & 15;        // key / d-col direction
    const int ty = tid >> 4;        // query direction
    const int q0 = qt * 64;
    const int bh = b * NH + h;

    const float* Qg = g_Q + (size_t)bh * Sq * HD;
    const float* Kg = g_K + (size_t)bh * SK * HD;
    const float* Vg = g_V + (size_t)bh * SK * HD;

    // load Q tile transposed
    #pragma unroll
    for (int t = 0; t < 4; t++) {
        const int lin = tid + t * 256;
        const int q   = lin >> 4;
        const int dd  = (lin & 15) * 4;
        float4 v = make_float4(0.f, 0.f, 0.f, 0.f);
        if (q0 + q < Sq) v = *(const float4*)&Qg[(size_t)(q0 + q) * HD + dd];
        Qs[(dd + 0) * STRD + q] = v.x;
        Qs[(dd + 1) * STRD + q] = v.y;
        Qs[(dd + 2) * STRD + q] = v.z;
        Qs[(dd + 3) * STRD + q] = v.w;
    }

    float m_r[4], l_r[4], o_r[4][4];
    #pragma unroll
    for (int qq = 0; qq < 4; qq++) {
        m_r[qq] = -1e30f;
        l_r[qq] = 0.0f;
        #pragma unroll
        for (int dd = 0; dd < 4; dd++) o_r[qq][dd] = 0.0f;
    }

    const int ntiles = min(16, qt + 2);   // causal trim

    for (int kt = 0; kt < ntiles; kt++) {
        __syncthreads();                   // previous readers of Ks/Vs done
        const int kb = kt * 64;
        #pragma unroll
        for (int t = 0; t < 4; t++) {
            const int lin = tid + t * 256;
            const int k   = lin >> 4;
            const int dd  = (lin & 15) * 4;
            float4 kvv = *(const float4*)&Kg[(size_t)(kb + k) * HD + dd];
            Ks[(dd + 0) * STRD + k] = kvv.x;
            Ks[(dd + 1) * STRD + k] = kvv.y;
            Ks[(dd + 2) * STRD + k] = kvv.z;
            Ks[(dd + 3) * STRD + k] = kvv.w;
            float4 vvv = *(const float4*)&Vg[(size_t)(kb + k) * HD + dd];
            *(float4*)&Vs[k * STRD + dd] = vvv;
        }
        __syncthreads();

        // S = Q K^T for this tile: 4q x 4k per thread
        float s[4][4];
        #pragma unroll
        for (int qq = 0; qq < 4; qq++)
            #pragma unroll
            for (int kk = 0; kk < 4; kk++) s[qq][kk] = 0.0f;

        #pragma unroll 8
        for (int d = 0; d < 64; d++) {
            float4 kv = *(const float4*)&Ks[d * STRD + tx * 4];
            float4 qv = *(const float4*)&Qs[d * STRD + ty * 4];
            float qa[4] = {qv.x, qv.y, qv.z, qv.w};
            float ka[4] = {kv.x, kv.y, kv.z, kv.w};
            #pragma unroll
            for (int qq = 0; qq < 4; qq++)
                #pragma unroll
                for (int kk = 0; kk < 4; kk++)
                    s[qq][kk] = fmaf(qa[qq], ka[kk], s[qq][kk]);
        }

        // scale + causal mask + attention mask
        float amv[4];
        #pragma unroll
        for (int kk = 0; kk < 4; kk++) {
            const int j = kb + tx * 4 + kk;
            amv[kk] = (j == 0) ? 0.0f : am[b * Sq + (j - 1)];
        }
        #pragma unroll
        for (int qq = 0; qq < 4; qq++) {
            const int qg = q0 + ty * 4 + qq;
            #pragma unroll
            for (int kk = 0; kk < 4; kk++) {
                const int j = kb + tx * 4 + kk;
                float v = (j <= qg + 1) ? s[qq][kk] * 0.125f : -10000.0f;
                s[qq][kk] = v + amv[kk];
            }
        }

        // online softmax (reduce over the 16-lane tx group)
        #pragma unroll
        for (int qq = 0; qq < 4; qq++) {
            float rm = fmaxf(fmaxf(s[qq][0], s[qq][1]), fmaxf(s[qq][2], s[qq][3]));
            #pragma unroll
            for (int off = 8; off >= 1; off >>= 1)
                rm = fmaxf(rm, __shfl_xor_sync(0xffffffffu, rm, off, 32));
            const float nm   = fmaxf(m_r[qq], rm);
            const float corr = __expf(m_r[qq] - nm);
            m_r[qq] = nm;
            float rs = 0.0f;
            #pragma unroll
            for (int kk = 0; kk < 4; kk++) {
                s[qq][kk] = __expf(s[qq][kk] - nm);
                rs += s[qq][kk];
            }
            #pragma unroll
            for (int off = 8; off >= 1; off >>= 1)
                rs += __shfl_xor_sync(0xffffffffu, rs, off, 32);
            l_r[qq] = l_r[qq] * corr + rs;
            #pragma unroll
            for (int dd = 0; dd < 4; dd++) o_r[qq][dd] *= corr;
        }

        __syncthreads();                   // everyone done reading Ks
        // write P over Ks
        #pragma unroll
        for (int qq = 0; qq < 4; qq++)
            *(float4*)&Ks[(ty * 4 + qq) * STRD + tx * 4] =
                make_float4(s[qq][0], s[qq][1], s[qq][2], s[qq][3]);
        __syncthreads();

        // O += P @ V
        #pragma unroll 8
        for (int k = 0; k < 64; k++) {
            float4 vv = *(const float4*)&Vs[k * STRD + tx * 4];
            float va[4] = {vv.x, vv.y, vv.z, vv.w};
            #pragma unroll
            for (int qq = 0; qq < 4; qq++) {
                const float p = Ks[(ty * 4 + qq) * STRD + k];
                #pragma unroll
                for (int dd = 0; dd < 4; dd++)
                    o_r[qq][dd] = fmaf(p, va[dd], o_r[qq][dd]);
            }
        }
    }

    // epilogue: normalize and store to g_AO (b,s,e) layout
    #pragma unroll
    for (int qq = 0; qq < 4; qq++) {
        const int qg = q0 + ty * 4 + qq;
        if (qg >= Sq) continue;
        const float inv = 1.0f / l_r[qq];
        float4 r = make_float4(o_r[qq][0] * inv, o_r[qq][1] * inv,
                               o_r[qq][2] * inv, o_r[qq][3] * inv);
        *(float4*)&g_AO[((size_t)(b * Sq + qg)) * EMB + h * HD + tx * 4] = r;
    }
}

// =====================================================================
// Kernel 4: output projection  out = g_AO(4092x1024) @ c_proj_w + b
// =====================================================================
__global__ __launch_bounds__(256, 2)
void proj_gemm_kernel(const float* __restrict__ W,
                      const float* __restrict__ bias,
                      float* __restrict__ out)
{
    __shared__ float As[BKK][BM];
    __shared__ float Bs[BKK][BN];

    const int tid = threadIdx.x;
    const int tx  = tid & 15;
    const int ty  = tid >> 4;
    const int bm  = blockIdx.y * BM;
    const int bn  = blockIdx.x * BN;

    const int a_m = tid >> 1;
    const int a_k = (tid & 1) * 4;
    const int b_k = tid >> 5;
    const int b_n = (tid & 31) * 4;

    float acc[8][8];
    #pragma unroll
    for (int i = 0; i < 8; i++)
        #pragma unroll
        for (int j = 0; j < 8; j++) acc[i][j] = 0.0f;

    const int Ktot = EMB, Ntot = EMB;
    const float* A = g_AO;

    for (int k0 = 0; k0 < Ktot; k0 += BKK) {
        float4 av = make_float4(0.f, 0.f, 0.f, 0.f);
        const int gm = bm + a_m;
        if (gm < MTOT) av = *(const float4*)&A[(size_t)gm * Ktot + k0 + a_k];
        As[a_k + 0][a_m] = av.x;
        As[a_k + 1][a_m] = av.y;
        As[a_k + 2][a_m] = av.z;
        As[a_k + 3][a_m] = av.w;

        float4 bv = *(const float4*)&W[(size_t)(k0 + b_k) * Ntot + bn + b_n];
        *(float4*)&Bs[b_k][b_n] = bv;
        __syncthreads();

        #pragma unroll
        for (int kk = 0; kk < BKK; kk++) {
            float a[8], b[8];
            *(float4*)&a[0] = *(const float4*)&As[kk][ty * 8];
            *(float4*)&a[4] = *(const float4*)&As[kk][ty * 8 + 4];
            *(float4*)&b[0] = *(const float4*)&Bs[kk][tx * 8];
            *(float4*)&b[4] = *(const float4*)&Bs[kk][tx * 8 + 4];
            #pragma unroll
            for (int i = 0; i < 8; i++)
                #pragma unroll
                for (int j = 0; j < 8; j++)
                    acc[i][j] = fmaf(a[i], b[j], acc[i][j]);
        }
        __syncthreads();
    }

    #pragma unroll
    for (int i = 0; i < 8; i++) {
        const int m = bm + ty * 8 + i;
        if (m >= MTOT) continue;
        #pragma unroll
        for (int j = 0; j < 8; j += 4) {
            const int n = bn + tx * 8 + j;
            float4 r = make_float4(acc[i][j + 0] + bias[n + 0],
                                   acc[i][j + 1] + bias[n + 1],
                                   acc[i][j + 2] + bias[n + 2],
                                   acc[i][j + 3] + bias[n + 3]);
            *(float4*)&out[(size_t)m * Ntot + n] = r;
        }
    }
}

// =====================================================================
// launch
// =====================================================================
extern "C" void kernel_launch(void* const* d_in, const int* in_sizes, int n_in,
                              void* d_out, int out_size)
{
    const float* word = (const float*)d_in[0];
    const float* img  = (const float*)d_in[1];
    const float* am   = (const float*)d_in[2];
    const float* caw  = (const float*)d_in[3];
    const float* cab  = (const float*)d_in[4];
    const float* cpw  = (const float*)d_in[5];
    const float* cpb  = (const float*)d_in[6];
    const float* ukw  = (const float*)d_in[7];
    const float* ukb  = (const float*)d_in[8];
    const float* uvw  = (const float*)d_in[9];
    const float* uvb  = (const float*)d_in[10];
    float* out = (float*)d_out;

    cudaFuncSetAttribute(attn_kernel,
                         cudaFuncAttributeMaxDynamicSharedMemorySize, ATTN_SMEM);

    qkv_gemm_kernel<<<dim3(24, 32), 256>>>(word, caw, cab);
    imgkv_kernel<<<1024, 256>>>(img, ukw, ukb, uvw, uvb);
    attn_kernel<<<dim3(16, NH, Bq), 256, ATTN_SMEM>>>(am);
    proj_gemm_kernel<<<dim3(8, 32), 256>>>(cpw, cpb, out);
}

// round 10
// speedup vs baseline: 1.8731x; 1.8731x over previous
#include <cuda_runtime.h>
#include <cuda_bf16.h>
#include <cstdint>

// Problem constants
#define Bq   4
#define Sq   1023
#define SK   1024
#define EMB  1024
#define NH   16
#define HD   64
#define MTOT (Bq*Sq)        // 4092
#define MPAD 4096

// -------- scratch (device globals; no runtime allocation allowed) --------
__device__ float g_Q [Bq*NH*Sq*HD];
__device__ float g_K [Bq*NH*SK*HD];
__device__ float g_V [Bq*NH*SK*HD];
// bf16 hi/lo split operands for tensor-core GEMMs
__device__ __nv_bfloat16 g_Ahi [MPAD*EMB],   g_Alo [MPAD*EMB];    // word states
__device__ __nv_bfloat16 g_Wqhi[3*EMB*EMB],  g_Wqlo[3*EMB*EMB];   // c_attn_w^T  [n][k]
__device__ __nv_bfloat16 g_Wphi[EMB*EMB],    g_Wplo[EMB*EMB];     // c_proj_w^T  [n][k]
__device__ __nv_bfloat16 g_AOhi[MPAD*EMB],   g_AOlo[MPAD*EMB];    // attn output

// ===================== PTX helpers (compute_103-safe: sm_80 era) =====================
__device__ __forceinline__ uint32_t smem_u32(const void* p) {
    uint32_t a;
    asm("{ .reg .u64 t; cvta.to.shared.u64 t, %1; cvt.u32.u64 %0, t; }"
        : "=r"(a) : "l"(p));
    return a;
}

__device__ __forceinline__ void cp16(uint32_t dst, const void* src) {
    asm volatile("cp.async.cg.shared.global [%0], [%1], 16;"
                 :: "r"(dst), "l"(src) : "memory");
}
#define CP_COMMIT() asm volatile("cp.async.commit_group;" ::: "memory")
#define CP_WAIT0()  asm volatile("cp.async.wait_group 0;" ::: "memory")

__device__ __forceinline__ void ldm4(uint32_t* r, uint32_t addr) {
    asm volatile("ldmatrix.sync.aligned.m8n8.x4.shared.b16 {%0,%1,%2,%3}, [%4];"
                 : "=r"(r[0]), "=r"(r[1]), "=r"(r[2]), "=r"(r[3]) : "r"(addr));
}

__device__ __forceinline__ void mma16816(float* c, const uint32_t* a, const uint32_t* b) {
    asm volatile(
        "mma.sync.aligned.m16n8k16.row.col.f32.bf16.bf16.f32 "
        "{%0,%1,%2,%3}, {%4,%5,%6,%7}, {%8,%9}, {%0,%1,%2,%3};"
        : "+f"(c[0]), "+f"(c[1]), "+f"(c[2]), "+f"(c[3])
        : "r"(a[0]), "r"(a[1]), "r"(a[2]), "r"(a[3]), "r"(b[0]), "r"(b[1]));
}

// =====================================================================
// Convert kernels (fp32 -> bf16 hi/lo split)
// =====================================================================
__global__ __launch_bounds__(256)
void conva_kernel(const float* __restrict__ word)
{
    const int idx = blockIdx.x * 256 + threadIdx.x;   // MPAD*EMB/4 threads
    const int m = idx >> 8;
    const int c = (idx & 255) * 4;
    float4 v = make_float4(0.f, 0.f, 0.f, 0.f);
    if (m < MTOT) v = *(const float4*)&word[(size_t)m * EMB + c];
    const size_t o = (size_t)m * EMB + c;
    __nv_bfloat16 h0 = __float2bfloat16(v.x), h1 = __float2bfloat16(v.y);
    __nv_bfloat16 h2 = __float2bfloat16(v.z), h3 = __float2bfloat16(v.w);
    __nv_bfloat16 l0 = __float2bfloat16(v.x - __bfloat162float(h0));
    __nv_bfloat16 l1 = __float2bfloat16(v.y - __bfloat162float(h1));
    __nv_bfloat16 l2 = __float2bfloat16(v.z - __bfloat162float(h2));
    __nv_bfloat16 l3 = __float2bfloat16(v.w - __bfloat162float(h3));
    __nv_bfloat162 p;
    p.x = h0; p.y = h1; *(__nv_bfloat162*)&g_Ahi[o]     = p;
    p.x = h2; p.y = h3; *(__nv_bfloat162*)&g_Ahi[o + 2] = p;
    p.x = l0; p.y = l1; *(__nv_bfloat162*)&g_Alo[o]     = p;
    p.x = l2; p.y = l3; *(__nv_bfloat162*)&g_Alo[o + 2] = p;
}

// transpose + convert: W[K=1024][N] -> Dhi/Dlo[N][1024]
__global__ __launch_bounds__(256)
void wconv_kernel(const float* __restrict__ W, int N, int mode)
{
    __shared__ float t[32][33];
    const int nx = blockIdx.x * 32, ky = blockIdx.y * 32;
    const int tx = threadIdx.x, ty = threadIdx.y;
    #pragma unroll
    for (int i = 0; i < 32; i += 8)
        t[ty + i][tx] = W[(size_t)(ky + ty + i) * N + nx + tx];
    __syncthreads();
    __nv_bfloat16* Dh = mode ? g_Wphi : g_Wqhi;
    __nv_bfloat16* Dl = mode ? g_Wplo : g_Wqlo;
    #pragma unroll
    for (int i = 0; i < 32; i += 8) {
        const float v = t[tx][ty + i];
        const int n = nx + ty + i, k = ky + tx;
        const __nv_bfloat16 h = __float2bfloat16(v);
        Dh[(size_t)n * EMB + k] = h;
        Dl[(size_t)n * EMB + k] = __float2bfloat16(v - __bfloat162float(h));
    }
}

__global__ __launch_bounds__(256)
void pad_ao_kernel()
{
    const int i = blockIdx.x * 256 + threadIdx.x;     // (MPAD-MTOT) rows * 1024
    if (i < (MPAD - MTOT) * EMB) {
        g_AOhi[(size_t)MTOT * EMB + i] = __float2bfloat16(0.f);
        g_AOlo[(size_t)MTOT * EMB + i] = __float2bfloat16(0.f);
    }
}

// =====================================================================
// mma.sync bf16 split GEMM: 128x128 CTA tile, BK=32, 8 warps (32x64 each).
// 3 MMA passes per k-step (hi*hi + lo*hi + hi*lo) -> ~fp32 accuracy.
// mode 0: qkv (scatter into g_Q/g_K/g_V); mode 1: proj (write out).
// =====================================================================
#define GBK   32
#define GSTR  40                    // smem row stride in bf16 elems (80B: conflict-free)
#define MATB  (128 * GSTR * 2)      // one 128xGBK matrix in bytes = 10240
#define BUFB  (4 * MATB)            // Ahi|Alo|Bhi|Blo = 40960
#define GSMEM (2 * BUFB)            // double buffered = 81920
#define NCH   (EMB / GBK)           // 32 chunks

__device__ __forceinline__ void gload(uint32_t dstbase, int tid, int k0, int bm, int bn,
                                      const __nv_bfloat16* __restrict__ Ahi,
                                      const __nv_bfloat16* __restrict__ Alo,
                                      const __nv_bfloat16* __restrict__ Bhi,
                                      const __nv_bfloat16* __restrict__ Blo)
{
    #pragma unroll
    for (int t = 0; t < 8; t++) {
        const int i   = tid + t * 256;      // 0..2047
        const int mat = i >> 9;             // 0..3
        const int r   = (i >> 2) & 127;
        const int seg = i & 3;
        const uint32_t dst = dstbase + mat * MATB + r * (GSTR * 2) + seg * 16;
        const __nv_bfloat16* src = (mat == 0) ? Ahi : (mat == 1) ? Alo
                                 : (mat == 2) ? Bhi : Blo;
        const int grow = ((mat < 2) ? bm : bn) + r;
        cp16(dst, src + (size_t)grow * EMB + k0 + seg * 8);
    }
    CP_COMMIT();
}

__global__ __launch_bounds__(256)
void gemm_mma_kernel(const float* __restrict__ bias, float* __restrict__ out, int mode)
{
    extern __shared__ __nv_bfloat16 smg[];
    const uint32_t sb = smem_u32(smg);

    const int tid  = threadIdx.x;
    const int warp = tid >> 5;
    const int lane = tid & 31;
    const int bn = blockIdx.x * 128;
    const int bm = blockIdx.y * 128;
    const int wm = (warp & 3) * 32;       // warp M offset
    const int wn = (warp >> 2) * 64;      // warp N offset

    const __nv_bfloat16* Ahi = mode ? g_AOhi : g_Ahi;
    const __nv_bfloat16* Alo = mode ? g_AOlo : g_Alo;
    const __nv_bfloat16* Bhi = mode ? g_Wphi : g_Wqhi;
    const __nv_bfloat16* Blo = mode ? g_Wplo : g_Wqlo;

    float acc[2][8][4];
    #pragma unroll
    for (int i = 0; i < 2; i++)
        #pragma unroll
        for (int j = 0; j < 8; j++)
            #pragma unroll
            for (int k = 0; k < 4; k++) acc[i][j][k] = 0.0f;

    gload(sb, tid, 0, bm, bn, Ahi, Alo, Bhi, Blo);

    for (int c = 0; c < NCH; c++) {
        CP_WAIT0();
        __syncthreads();
        if (c + 1 < NCH)
            gload(sb + ((c + 1) & 1) * BUFB, tid, (c + 1) * GBK, bm, bn, Ahi, Alo, Bhi, Blo);

        const uint32_t cb = sb + (c & 1) * BUFB;

        #pragma unroll
        for (int ks = 0; ks < GBK; ks += 16) {
            uint32_t ahi[2][4], alo[2][4], bhi[8][2], blo[8][2];
            // A fragments: ldmatrix.x4, rows m0+(lane&15), col ks+(lane>>4)*8
            #pragma unroll
            for (int mt = 0; mt < 2; mt++) {
                const uint32_t ra = cb + (wm + mt * 16 + (lane & 15)) * (GSTR * 2)
                                       + (ks + (lane >> 4) * 8) * 2;
                ldm4(ahi[mt], ra);
                ldm4(alo[mt], ra + MATB);
            }
            // B fragments: pairs of n-tiles per x4
            #pragma unroll
            for (int p = 0; p < 4; p++) {
                const uint32_t rowb = wn + p * 16 + (lane & 7) + ((lane >> 4) << 3);
                const uint32_t rb = cb + 2 * MATB + rowb * (GSTR * 2)
                                       + (ks + ((lane >> 3) & 1) * 8) * 2;
                uint32_t r4[4];
                ldm4(r4, rb);
                bhi[p*2][0] = r4[0]; bhi[p*2][1] = r4[1];
                bhi[p*2+1][0] = r4[2]; bhi[p*2+1][1] = r4[3];
                ldm4(r4, rb + MATB);
                blo[p*2][0] = r4[0]; blo[p*2][1] = r4[1];
                blo[p*2+1][0] = r4[2]; blo[p*2+1][1] = r4[3];
            }
            #pragma unroll
            for (int mt = 0; mt < 2; mt++)
                #pragma unroll
                for (int nt = 0; nt < 8; nt++) {
                    mma16816(acc[mt][nt], ahi[mt], bhi[nt]);
                    mma16816(acc[mt][nt], alo[mt], bhi[nt]);
                    mma16816(acc[mt][nt], ahi[mt], blo[nt]);
                }
        }
    }

    // ---- epilogue: fragment -> global (float2 contiguous in n) ----
    #pragma unroll
    for (int mt = 0; mt < 2; mt++) {
        #pragma unroll
        for (int nt = 0; nt < 8; nt++) {
            const int n = bn + wn + nt * 8 + (lane & 3) * 2;
            const float2 bv = *(const float2*)&bias[n];
            #pragma unroll
            for (int half = 0; half < 2; half++) {
                const int m = bm + wm + mt * 16 + (lane >> 2) + half * 8;
                if (m >= MTOT) continue;
                float2 v = make_float2(acc[mt][nt][half*2+0] + bv.x,
                                       acc[mt][nt][half*2+1] + bv.y);
                if (mode == 0) {
                    const int b_ = m / Sq;
                    const int s  = m - b_ * Sq;
                    const int sec = n >> 10;
                    const int e = n & 1023, h = e >> 6, d = e & 63;
                    float* dst;
                    if (sec == 0)
                        dst = &g_Q[(((size_t)(b_ * NH + h)) * Sq + s) * HD + d];
                    else if (sec == 1)
                        dst = &g_K[(((size_t)(b_ * NH + h)) * SK + s + 1) * HD + d];
                    else
                        dst = &g_V[(((size_t)(b_ * NH + h)) * SK + s + 1) * HD + d];
                    *(float2*)dst = v;
                } else {
                    *(float2*)&out[(size_t)m * EMB + n] = v;
                }
            }
        }
    }
}

// =====================================================================
// image k/v
// =====================================================================
__global__ __launch_bounds__(256)
void imgkv_kernel(const float* __restrict__ img,
                  const float* __restrict__ ukw, const float* __restrict__ ukb,
                  const float* __restrict__ uvw, const float* __restrict__ uvb)
{
    const int warp = threadIdx.x >> 5;
    const int lane = threadIdx.x & 31;
    const int idx  = blockIdx.x * 8 + warp;
    const int kv   = idx >> 12;
    const int rem  = idx & 4095;
    const int b    = rem >> 10;
    const int e    = rem & 1023;

    const float* w = (kv == 0 ? ukw : uvw) + (size_t)e * EMB;
    const float* x = img + (size_t)b * EMB;

    float s = 0.0f;
    #pragma unroll
    for (int t = 0; t < 8; t++) {
        const int f = (lane + t * 32) * 4;
        float4 wv = *(const float4*)&w[f];
        float4 xv = *(const float4*)&x[f];
        s = fmaf(wv.x, xv.x, s);
        s = fmaf(wv.y, xv.y, s);
        s = fmaf(wv.z, xv.z, s);
        s = fmaf(wv.w, xv.w, s);
    }
    #pragma unroll
    for (int off = 16; off >= 1; off >>= 1)
        s += __shfl_xor_sync(0xffffffffu, s, off, 32);

    if (lane == 0) {
        const float bv = (kv == 0 ? ukb : uvb)[e];
        const int h = e >> 6, d = e & 63;
        float* dst = (kv == 0 ? g_K : g_V);
        dst[(((size_t)(b * NH + h)) * SK + 0) * HD + d] = s + bv;
    }
}

// =====================================================================
// flash attention, fp32; epilogue writes bf16 hi/lo for the proj GEMM
// =====================================================================
#define STRD 68
#define ATTN_SMEM (3 * 64 * STRD * 4)

__global__ __launch_bounds__(256)
void attn_kernel(const float* __restrict__ am)
{
    extern __shared__ float sm[];
    float* Qs = sm;
    float* Ks = sm + 64 * STRD;
    float* Vs = sm + 2 * 64 * STRD;

    const int b  = blockIdx.z;
    const int h  = blockIdx.y;
    const int qt = blockIdx.x;
    const int tid = threadIdx.x;
    const int tx = tid & 15;
    const int ty = tid >> 4;
    const int q0 = qt * 64;
    const int bh = b * NH + h;

    const float* Qg = g_Q + (size_t)bh * Sq * HD;
    const float* Kg = g_K + (size_t)bh * SK * HD;
    const float* Vg = g_V + (size_t)bh * SK * HD;

    #pragma unroll
    for (int t = 0; t < 4; t++) {
        const int lin = tid + t * 256;
        const int q   = lin >> 4;
        const int dd  = (lin & 15) * 4;
        float4 v = make_float4(0.f, 0.f, 0.f, 0.f);
        if (q0 + q < Sq) v = *(const float4*)&Qg[(size_t)(q0 + q) * HD + dd];
        Qs[(dd + 0) * STRD + q] = v.x;
        Qs[(dd + 1) * STRD + q] = v.y;
        Qs[(dd + 2) * STRD + q] = v.z;
        Qs[(dd + 3) * STRD + q] = v.w;
    }

    float m_r[4], l_r[4], o_r[4][4];
    #pragma unroll
    for (int qq = 0; qq < 4; qq++) {
        m_r[qq] = -1e30f;
        l_r[qq] = 0.0f;
        #pragma unroll
        for (int dd = 0; dd < 4; dd++) o_r[qq][dd] = 0.0f;
    }

    const int ntiles = min(16, qt + 2);

    for (int kt = 0; kt < ntiles; kt++) {
        __syncthreads();
        const int kb = kt * 64;
        #pragma unroll
        for (int t = 0; t < 4; t++) {
            const int lin = tid + t * 256;
            const int k   = lin >> 4;
            const int dd  = (lin & 15) * 4;
            float4 kvv = *(const float4*)&Kg[(size_t)(kb + k) * HD + dd];
            Ks[(dd + 0) * STRD + k] = kvv.x;
            Ks[(dd + 1) * STRD + k] = kvv.y;
            Ks[(dd + 2) * STRD + k] = kvv.z;
            Ks[(dd + 3) * STRD + k] = kvv.w;
            float4 vvv = *(const float4*)&Vg[(size_t)(kb + k) * HD + dd];
            *(float4*)&Vs[k * STRD + dd] = vvv;
        }
        __syncthreads();

        float s[4][4];
        #pragma unroll
        for (int qq = 0; qq < 4; qq++)
            #pragma unroll
            for (int kk = 0; kk < 4; kk++) s[qq][kk] = 0.0f;

        #pragma unroll 8
        for (int d = 0; d < 64; d++) {
            float4 kv = *(const float4*)&Ks[d * STRD + tx * 4];
            float4 qv = *(const float4*)&Qs[d * STRD + ty * 4];
            float qa[4] = {qv.x, qv.y, qv.z, qv.w};
            float ka[4] = {kv.x, kv.y, kv.z, kv.w};
            #pragma unroll
            for (int qq = 0; qq < 4; qq++)
                #pragma unroll
                for (int kk = 0; kk < 4; kk++)
                    s[qq][kk] = fmaf(qa[qq], ka[kk], s[qq][kk]);
        }

        float amv[4];
        #pragma unroll
        for (int kk = 0; kk < 4; kk++) {
            const int j = kb + tx * 4 + kk;
            amv[kk] = (j == 0) ? 0.0f : am[b * Sq + (j - 1)];
        }
        #pragma unroll
        for (int qq = 0; qq < 4; qq++) {
            const int qg = q0 + ty * 4 + qq;
            #pragma unroll
            for (int kk = 0; kk < 4; kk++) {
                const int j = kb + tx * 4 + kk;
                float v = (j <= qg + 1) ? s[qq][kk] * 0.125f : -10000.0f;
                s[qq][kk] = v + amv[kk];
            }
        }

        #pragma unroll
        for (int qq = 0; qq < 4; qq++) {
            float rm = fmaxf(fmaxf(s[qq][0], s[qq][1]), fmaxf(s[qq][2], s[qq][3]));
            #pragma unroll
            for (int off = 8; off >= 1; off >>= 1)
                rm = fmaxf(rm, __shfl_xor_sync(0xffffffffu, rm, off, 32));
            const float nm   = fmaxf(m_r[qq], rm);
            const float corr = __expf(m_r[qq] - nm);
            m_r[qq] = nm;
            float rs = 0.0f;
            #pragma unroll
            for (int kk = 0; kk < 4; kk++) {
                s[qq][kk] = __expf(s[qq][kk] - nm);
                rs += s[qq][kk];
            }
            #pragma unroll
            for (int off = 8; off >= 1; off >>= 1)
                rs += __shfl_xor_sync(0xffffffffu, rs, off, 32);
            l_r[qq] = l_r[qq] * corr + rs;
            #pragma unroll
            for (int dd = 0; dd < 4; dd++) o_r[qq][dd] *= corr;
        }

        __syncthreads();
        #pragma unroll
        for (int qq = 0; qq < 4; qq++)
            *(float4*)&Ks[(ty * 4 + qq) * STRD + tx * 4] =
                make_float4(s[qq][0], s[qq][1], s[qq][2], s[qq][3]);
        __syncthreads();

        #pragma unroll 8
        for (int k = 0; k < 64; k++) {
            float4 vv = *(const float4*)&Vs[k * STRD + tx * 4];
            float va[4] = {vv.x, vv.y, vv.z, vv.w};
            #pragma unroll
            for (int qq = 0; qq < 4; qq++) {
                const float p = Ks[(ty * 4 + qq) * STRD + k];
                #pragma unroll
                for (int dd = 0; dd < 4; dd++)
                    o_r[qq][dd] = fmaf(p, va[dd], o_r[qq][dd]);
            }
        }
    }

    // epilogue: normalize, convert to bf16 hi/lo for the projection GEMM
    #pragma unroll
    for (int qq = 0; qq < 4; qq++) {
        const int qg = q0 + ty * 4 + qq;
        if (qg >= Sq) continue;
        const float inv = 1.0f / l_r[qq];
        const float v0 = o_r[qq][0] * inv, v1 = o_r[qq][1] * inv;
        const float v2 = o_r[qq][2] * inv, v3 = o_r[qq][3] * inv;
        const size_t off = ((size_t)(b * Sq + qg)) * EMB + h * HD + tx * 4;
        __nv_bfloat16 h0 = __float2bfloat16(v0), h1 = __float2bfloat16(v1);
        __nv_bfloat16 h2 = __float2bfloat16(v2), h3 = __float2bfloat16(v3);
        __nv_bfloat16 l0 = __float2bfloat16(v0 - __bfloat162float(h0));
        __nv_bfloat16 l1 = __float2bfloat16(v1 - __bfloat162float(h1));
        __nv_bfloat16 l2 = __float2bfloat16(v2 - __bfloat162float(h2));
        __nv_bfloat16 l3 = __float2bfloat16(v3 - __bfloat162float(h3));
        __nv_bfloat162 p;
        p.x = h0; p.y = h1; *(__nv_bfloat162*)&g_AOhi[off]     = p;
        p.x = h2; p.y = h3; *(__nv_bfloat162*)&g_AOhi[off + 2] = p;
        p.x = l0; p.y = l1; *(__nv_bfloat162*)&g_AOlo[off]     = p;
        p.x = l2; p.y = l3; *(__nv_bfloat162*)&g_AOlo[off + 2] = p;
    }
}

// =====================================================================
// launch
// =====================================================================
extern "C" void kernel_launch(void* const* d_in, const int* in_sizes, int n_in,
                              void* d_out, int out_size)
{
    const float* word = (const float*)d_in[0];
    const float* img  = (const float*)d_in[1];
    const float* am   = (const float*)d_in[2];
    const float* caw  = (const float*)d_in[3];
    const float* cab  = (const float*)d_in[4];
    const float* cpw  = (const float*)d_in[5];
    const float* cpb  = (const float*)d_in[6];
    const float* ukw  = (const float*)d_in[7];
    const float* ukb  = (const float*)d_in[8];
    const float* uvw  = (const float*)d_in[9];
    const float* uvb  = (const float*)d_in[10];
    float* out = (float*)d_out;

    cudaFuncSetAttribute(attn_kernel,
                         cudaFuncAttributeMaxDynamicSharedMemorySize, ATTN_SMEM);
    cudaFuncSetAttribute(gemm_mma_kernel,
                         cudaFuncAttributeMaxDynamicSharedMemorySize, GSMEM);

    conva_kernel<<<MPAD * EMB / 4 / 256, 256>>>(word);
    wconv_kernel<<<dim3(96, 32), dim3(32, 8)>>>(caw, 3 * EMB, 0);
    wconv_kernel<<<dim3(32, 32), dim3(32, 8)>>>(cpw, EMB, 1);
    pad_ao_kernel<<<16, 256>>>();

    gemm_mma_kernel<<<dim3(24, 32), 256, GSMEM>>>(cab, out, 0);     // qkv
    imgkv_kernel<<<1024, 256>>>(img, ukw, ukb, uvw, uvb);
    attn_kernel<<<dim3(16, NH, Bq), 256, ATTN_SMEM>>>(am);
    gemm_mma_kernel<<<dim3(8, 32), 256, GSMEM>>>(cpb, out, 1);      // proj
}

// round 12
// speedup vs baseline: 2.7809x; 1.4846x over previous
#include <cuda_runtime.h>
#include <cuda_bf16.h>
#include <cstdint>

// Problem constants
#define Bq   4
#define Sq   1023
#define SK   1024
#define EMB  1024
#define NH   16
#define HD   64
#define MTOT (Bq*Sq)        // 4092
#define MPAD 4096

// -------- scratch (device globals; no runtime allocation allowed) --------
// bf16 hi/lo split operands for tensor-core GEMMs
__device__ __nv_bfloat16 g_Ahi [MPAD*EMB],   g_Alo [MPAD*EMB];    // word states
__device__ __nv_bfloat16 g_Wqhi[3*EMB*EMB],  g_Wqlo[3*EMB*EMB];   // c_attn_w^T  [n][k]
__device__ __nv_bfloat16 g_Wphi[EMB*EMB],    g_Wplo[EMB*EMB];     // c_proj_w^T  [n][k]
__device__ __nv_bfloat16 g_AOhi[MPAD*EMB],   g_AOlo[MPAD*EMB];    // attn output
// bf16 hi/lo Q/K/V for tensor attention  [b][h][s|k][d]
__device__ __nv_bfloat16 g_Qh[Bq*NH*Sq*HD],  g_Ql[Bq*NH*Sq*HD];
__device__ __nv_bfloat16 g_Kh[Bq*NH*SK*HD],  g_Kl[Bq*NH*SK*HD];
__device__ __nv_bfloat16 g_Vh[Bq*NH*SK*HD],  g_Vl[Bq*NH*SK*HD];

// ===================== PTX helpers (compute_103-safe: sm_80 era) =====================
__device__ __forceinline__ uint32_t smem_u32(const void* p) {
    uint32_t a;
    asm("{ .reg .u64 t; cvta.to.shared.u64 t, %1; cvt.u32.u64 %0, t; }"
        : "=r"(a) : "l"(p));
    return a;
}

__device__ __forceinline__ void cp16(uint32_t dst, const void* src) {
    asm volatile("cp.async.cg.shared.global [%0], [%1], 16;"
                 :: "r"(dst), "l"(src) : "memory");
}
__device__ __forceinline__ void cp16z(uint32_t dst, const void* src, bool v) {
    int sz = v ? 16 : 0;
    asm volatile("cp.async.cg.shared.global [%0], [%1], 16, %2;"
                 :: "r"(dst), "l"(src), "r"(sz) : "memory");
}
#define CP_COMMIT() asm volatile("cp.async.commit_group;" ::: "memory")
#define CP_WAIT0()  asm volatile("cp.async.wait_group 0;" ::: "memory")

__device__ __forceinline__ void ldm4(uint32_t* r, uint32_t addr) {
    asm volatile("ldmatrix.sync.aligned.m8n8.x4.shared.b16 {%0,%1,%2,%3}, [%4];"
                 : "=r"(r[0]), "=r"(r[1]), "=r"(r[2]), "=r"(r[3]) : "r"(addr));
}
__device__ __forceinline__ void ldm4t(uint32_t* r, uint32_t addr) {
    asm volatile("ldmatrix.sync.aligned.m8n8.x4.trans.shared.b16 {%0,%1,%2,%3}, [%4];"
                 : "=r"(r[0]), "=r"(r[1]), "=r"(r[2]), "=r"(r[3]) : "r"(addr));
}

__device__ __forceinline__ void mma16816(float* c, const uint32_t* a, const uint32_t* b) {
    asm volatile(
        "mma.sync.aligned.m16n8k16.row.col.f32.bf16.bf16.f32 "
        "{%0,%1,%2,%3}, {%4,%5,%6,%7}, {%8,%9}, {%0,%1,%2,%3};"
        : "+f"(c[0]), "+f"(c[1]), "+f"(c[2]), "+f"(c[3])
        : "r"(a[0]), "r"(a[1]), "r"(a[2]), "r"(a[3]), "r"(b[0]), "r"(b[1]));
}

// fast e^x on the FMA pipe (x <= ~0; rel err ~2e-6); avoids MUFU throughput floor
__device__ __forceinline__ float fexp(float x) {
    float y = fmaxf(x * 1.4426950408889634f, -126.0f);
    int   n = __float2int_rn(y);
    float f = y - (float)n;
    float p = 1.3333558146e-3f;
    p = fmaf(p, f, 9.6181291076e-3f);
    p = fmaf(p, f, 5.5504108664e-2f);
    p = fmaf(p, f, 2.4022650696e-1f);
    p = fmaf(p, f, 6.9314718056e-1f);
    p = fmaf(p, f, 1.0f);
    return p * __int_as_float((n + 127) << 23);
}

// split a pair of fp32 into bf16 hi / lo packed registers (.x = first arg = low half)
__device__ __forceinline__ void split2(float a, float b, uint32_t& hi, uint32_t& lo) {
    __nv_bfloat162 h = __floats2bfloat162_rn(a, b);
    __nv_bfloat162 l = __floats2bfloat162_rn(a - __bfloat162float(h.x),
                                             b - __bfloat162float(h.y));
    hi = *(uint32_t*)&h;
    lo = *(uint32_t*)&l;
}

// =====================================================================
// Convert kernels (fp32 -> bf16 hi/lo split)
// =====================================================================
__global__ __launch_bounds__(256)
void conva_kernel(const float* __restrict__ word)
{
    const int idx = blockIdx.x * 256 + threadIdx.x;   // MPAD*EMB/4 threads
    const int m = idx >> 8;
    const int c = (idx & 255) * 4;
    float4 v = make_float4(0.f, 0.f, 0.f, 0.f);
    if (m < MTOT) v = *(const float4*)&word[(size_t)m * EMB + c];
    const size_t o = (size_t)m * EMB + c;
    uint32_t h0, l0, h1, l1;
    split2(v.x, v.y, h0, l0);
    split2(v.z, v.w, h1, l1);
    *(uint32_t*)&g_Ahi[o]     = h0;
    *(uint32_t*)&g_Ahi[o + 2] = h1;
    *(uint32_t*)&g_Alo[o]     = l0;
    *(uint32_t*)&g_Alo[o + 2] = l1;
}

// transpose + convert: W[K=1024][N] -> Dhi/Dlo[N][1024]
__global__ __launch_bounds__(256)
void wconv_kernel(const float* __restrict__ W, int N, int mode)
{
    __shared__ float t[32][33];
    const int nx = blockIdx.x * 32, ky = blockIdx.y * 32;
    const int tx = threadIdx.x, ty = threadIdx.y;
    #pragma unroll
    for (int i = 0; i < 32; i += 8)
        t[ty + i][tx] = W[(size_t)(ky + ty + i) * N + nx + tx];
    __syncthreads();
    __nv_bfloat16* Dh = mode ? g_Wphi : g_Wqhi;
    __nv_bfloat16* Dl = mode ? g_Wplo : g_Wqlo;
    #pragma unroll
    for (int i = 0; i < 32; i += 8) {
        const float v = t[tx][ty + i];
        const int n = nx + ty + i, k = ky + tx;
        const __nv_bfloat16 h = __float2bfloat16(v);
        Dh[(size_t)n * EMB + k] = h;
        Dl[(size_t)n * EMB + k] = __float2bfloat16(v - __bfloat162float(h));
    }
}

__global__ __launch_bounds__(256)
void pad_ao_kernel()
{
    const int i = blockIdx.x * 256 + threadIdx.x;     // (MPAD-MTOT) rows * 1024
    if (i < (MPAD - MTOT) * EMB) {
        g_AOhi[(size_t)MTOT * EMB + i] = __float2bfloat16(0.f);
        g_AOlo[(size_t)MTOT * EMB + i] = __float2bfloat16(0.f);
    }
}

// =====================================================================
// mma.sync bf16 split GEMM: 128x128 CTA tile, BK=32, 8 warps (32x64 each).
// mode 0: qkv (scatter bf16 hi/lo into g_Q*/g_K*/g_V*); mode 1: proj -> out.
// =====================================================================
#define GBK   32
#define GSTR  40
#define MATB  (128 * GSTR * 2)
#define BUFB  (4 * MATB)
#define GSMEM (2 * BUFB)
#define NCH   (EMB / GBK)

__device__ __forceinline__ void gload(uint32_t dstbase, int tid, int k0, int bm, int bn,
                                      const __nv_bfloat16* __restrict__ Ahi,
                                      const __nv_bfloat16* __restrict__ Alo,
                                      const __nv_bfloat16* __restrict__ Bhi,
                                      const __nv_bfloat16* __restrict__ Blo)
{
    #pragma unroll
    for (int t = 0; t < 8; t++) {
        const int i   = tid + t * 256;
        const int mat = i >> 9;
        const int r   = (i >> 2) & 127;
        const int seg = i & 3;
        const uint32_t dst = dstbase + mat * MATB + r * (GSTR * 2) + seg * 16;
        const __nv_bfloat16* src = (mat == 0) ? Ahi : (mat == 1) ? Alo
                                 : (mat == 2) ? Bhi : Blo;
        const int grow = ((mat < 2) ? bm : bn) + r;
        cp16(dst, src + (size_t)grow * EMB + k0 + seg * 8);
    }
    CP_COMMIT();
}

__global__ __launch_bounds__(256)
void gemm_mma_kernel(const float* __restrict__ bias, float* __restrict__ out, int mode)
{
    extern __shared__ __nv_bfloat16 smg[];
    const uint32_t sb = smem_u32(smg);

    const int tid  = threadIdx.x;
    const int warp = tid >> 5;
    const int lane = tid & 31;
    const int bn = blockIdx.x * 128;
    const int bm = blockIdx.y * 128;
    const int wm = (warp & 3) * 32;
    const int wn = (warp >> 2) * 64;

    const __nv_bfloat16* Ahi = mode ? g_AOhi : g_Ahi;
    const __nv_bfloat16* Alo = mode ? g_AOlo : g_Alo;
    const __nv_bfloat16* Bhi = mode ? g_Wphi : g_Wqhi;
    const __nv_bfloat16* Blo = mode ? g_Wplo : g_Wqlo;

    float acc[2][8][4];
    #pragma unroll
    for (int i = 0; i < 2; i++)
        #pragma unroll
        for (int j = 0; j < 8; j++)
            #pragma unroll
            for (int k = 0; k < 4; k++) acc[i][j][k] = 0.0f;

    gload(sb, tid, 0, bm, bn, Ahi, Alo, Bhi, Blo);

    for (int c = 0; c < NCH; c++) {
        CP_WAIT0();
        __syncthreads();
        if (c + 1 < NCH)
            gload(sb + ((c + 1) & 1) * BUFB, tid, (c + 1) * GBK, bm, bn, Ahi, Alo, Bhi, Blo);

        const uint32_t cb = sb + (c & 1) * BUFB;

        #pragma unroll
        for (int ks = 0; ks < GBK; ks += 16) {
            uint32_t ahi[2][4], alo[2][4], bhi[8][2], blo[8][2];
            #pragma unroll
            for (int mt = 0; mt < 2; mt++) {
                const uint32_t ra = cb + (wm + mt * 16 + (lane & 15)) * (GSTR * 2)
                                       + (ks + (lane >> 4) * 8) * 2;
                ldm4(ahi[mt], ra);
                ldm4(alo[mt], ra + MATB);
            }
            #pragma unroll
            for (int p = 0; p < 4; p++) {
                const uint32_t rowb = wn + p * 16 + (lane & 7) + ((lane >> 4) << 3);
                const uint32_t rb = cb + 2 * MATB + rowb * (GSTR * 2)
                                       + (ks + ((lane >> 3) & 1) * 8) * 2;
                uint32_t r4[4];
                ldm4(r4, rb);
                bhi[p*2][0] = r4[0]; bhi[p*2][1] = r4[1];
                bhi[p*2+1][0] = r4[2]; bhi[p*2+1][1] = r4[3];
                ldm4(r4, rb + MATB);
                blo[p*2][0] = r4[0]; blo[p*2][1] = r4[1];
                blo[p*2+1][0] = r4[2]; blo[p*2+1][1] = r4[3];
            }
            #pragma unroll
            for (int mt = 0; mt < 2; mt++)
                #pragma unroll
                for (int nt = 0; nt < 8; nt++) {
                    mma16816(acc[mt][nt], ahi[mt], bhi[nt]);
                    mma16816(acc[mt][nt], alo[mt], bhi[nt]);
                    mma16816(acc[mt][nt], ahi[mt], blo[nt]);
                }
        }
    }

    // ---- epilogue ----
    #pragma unroll
    for (int mt = 0; mt < 2; mt++) {
        #pragma unroll
        for (int nt = 0; nt < 8; nt++) {
            const int n = bn + wn + nt * 8 + (lane & 3) * 2;
            const float2 bv = *(const float2*)&bias[n];
            #pragma unroll
            for (int half = 0; half < 2; half++) {
                const int m = bm + wm + mt * 16 + (lane >> 2) + half * 8;
                if (m >= MTOT) continue;
                float2 v = make_float2(acc[mt][nt][half*2+0] + bv.x,
                                       acc[mt][nt][half*2+1] + bv.y);
                if (mode == 0) {
                    const int b_ = m / Sq;
                    const int s  = m - b_ * Sq;
                    const int sec = n >> 10;
                    const int e = n & 1023, h = e >> 6, d = e & 63;
                    uint32_t hu, lu;
                    split2(v.x, v.y, hu, lu);
                    size_t off;
                    __nv_bfloat16 *dh, *dl;
                    if (sec == 0) {
                        off = ((size_t)(b_ * NH + h) * Sq + s) * HD + d;
                        dh = g_Qh; dl = g_Ql;
                    } else if (sec == 1) {
                        off = ((size_t)(b_ * NH + h) * SK + s + 1) * HD + d;
                        dh = g_Kh; dl = g_Kl;
                    } else {
                        off = ((size_t)(b_ * NH + h) * SK + s + 1) * HD + d;
                        dh = g_Vh; dl = g_Vl;
                    }
                    *(uint32_t*)&dh[off] = hu;
                    *(uint32_t*)&dl[off] = lu;
                } else {
                    *(float2*)&out[(size_t)m * EMB + n] = v;
                }
            }
        }
    }
}

// =====================================================================
// image k/v -> key/value slot 0, bf16 hi/lo
// =====================================================================
__global__ __launch_bounds__(256)
void imgkv_kernel(const float* __restrict__ img,
                  const float* __restrict__ ukw, const float* __restrict__ ukb,
                  const float* __restrict__ uvw, const float* __restrict__ uvb)
{
    const int warp = threadIdx.x >> 5;
    const int lane = threadIdx.x & 31;
    const int idx  = blockIdx.x * 8 + warp;
    const int kv   = idx >> 12;
    const int rem  = idx & 4095;
    const int b    = rem >> 10;
    const int e    = rem & 1023;

    const float* w = (kv == 0 ? ukw : uvw) + (size_t)e * EMB;
    const float* x = img + (size_t)b * EMB;

    float s = 0.0f;
    #pragma unroll
    for (int t = 0; t < 8; t++) {
        const int f = (lane + t * 32) * 4;
        float4 wv = *(const float4*)&w[f];
        float4 xv = *(const float4*)&x[f];
        s = fmaf(wv.x, xv.x, s);
        s = fmaf(wv.y, xv.y, s);
        s = fmaf(wv.z, xv.z, s);
        s = fmaf(wv.w, xv.w, s);
    }
    #pragma unroll
    for (int off = 16; off >= 1; off >>= 1)
        s += __shfl_xor_sync(0xffffffffu, s, off, 32);

    if (lane == 0) {
        const float v = s + (kv == 0 ? ukb : uvb)[e];
        const int h = e >> 6, d = e & 63;
        const size_t off = ((size_t)(b * NH + h) * SK + 0) * HD + d;
        const __nv_bfloat16 hh = __float2bfloat16(v);
        const __nv_bfloat16 ll = __float2bfloat16(v - __bfloat162float(hh));
        if (kv == 0) { g_Kh[off] = hh; g_Kl[off] = ll; }
        else         { g_Vh[off] = hh; g_Vl[off] = ll; }
    }
}

// =====================================================================
// tensor-core flash attention (split bf16, 3-pass QK^T and PV).
// CTA: 128 threads = 4 warps, 64 queries; stream 64-key tiles.
// smem: Qhi|Qlo | 2 x {Khi,Klo,Vhi,Vlo}; stride 72 (conflict-free ldmatrix).
// =====================================================================
#define ASTR    72
#define ATILE_B (64 * ASTR * 2)      // 9216
#define ATTN_SMEM (10 * ATILE_B)     // 92160

__device__ __forceinline__ void attn_ldkv(uint32_t dst, int tid, int kb,
    const __nv_bfloat16* __restrict__ Khp, const __nv_bfloat16* __restrict__ Klp,
    const __nv_bfloat16* __restrict__ Vhp, const __nv_bfloat16* __restrict__ Vlp)
{
    #pragma unroll
    for (int t = 0; t < 16; t++) {
        const int i   = tid + t * 128;      // 0..2047
        const int mat = i >> 9;             // 0..3
        const int r   = (i >> 3) & 63;
        const int seg = i & 7;
        const __nv_bfloat16* src =
            (mat == 0 ? Khp : mat == 1 ? Klp : mat == 2 ? Vhp : Vlp)
            + (size_t)(kb + r) * HD + seg * 8;
        cp16(dst + mat * ATILE_B + r * (ASTR * 2) + seg * 16, src);
    }
    CP_COMMIT();
}

__global__ __launch_bounds__(128)
void attn_kernel(const float* __restrict__ am)
{
    extern __shared__ char smA[];
    const uint32_t sb = smem_u32(smA);

    const int b  = blockIdx.z;
    const int h  = blockIdx.y;
    const int qt = blockIdx.x;
    const int tid  = threadIdx.x;
    const int warp = tid >> 5;
    const int lane = tid & 31;
    const int q4 = lane & 3;
    const int r8 = lane >> 2;
    const int wm = warp * 16;
    const int q0 = qt * 64;
    const int bh = b * NH + h;
    const int bSq = b * Sq;

    const __nv_bfloat16* Khp = g_Kh + (size_t)bh * SK * HD;
    const __nv_bfloat16* Klp = g_Kl + (size_t)bh * SK * HD;
    const __nv_bfloat16* Vhp = g_Vh + (size_t)bh * SK * HD;
    const __nv_bfloat16* Vlp = g_Vl + (size_t)bh * SK * HD;

    // --- load Q tile (hi/lo) + first K/V tile ---
    #pragma unroll
    for (int t = 0; t < 8; t++) {
        const int i   = tid + t * 128;      // 0..1023
        const int mat = i >> 9;             // 0..1
        const int r   = (i >> 3) & 63;
        const int seg = i & 7;
        const int row = q0 + r;
        const bool v = row < Sq;
        const __nv_bfloat16* src = (mat ? g_Ql : g_Qh)
            + ((size_t)bh * Sq + (v ? row : 0)) * HD + seg * 8;
        cp16z(sb + mat * ATILE_B + r * (ASTR * 2) + seg * 16, src, v);
    }
    attn_ldkv(sb + 2 * ATILE_B, tid, 0, Khp, Klp, Vhp, Vlp);
    CP_WAIT0();
    __syncthreads();

    // Q fragments (A operand, m16k16 x4 ksteps), loaded once
    uint32_t qhi[4][4], qlo[4][4];
    #pragma unroll
    for (int kk = 0; kk < 4; kk++) {
        const uint32_t ra = sb + (wm + (lane & 15)) * (ASTR * 2)
                               + (kk * 16 + (lane >> 4) * 8) * 2;
        ldm4(qhi[kk], ra);
        ldm4(qlo[kk], ra + ATILE_B);
    }

    float o[8][4];
    #pragma unroll
    for (int i = 0; i < 8; i++)
        #pragma unroll
        for (int j = 0; j < 4; j++) o[i][j] = 0.0f;
    float m0 = -1e30f, m1 = -1e30f, l0 = 0.0f, l1 = 0.0f;

    const int ntl = min(16, qt + 2);
    const int i0 = q0 + wm + r8;
    const int i1 = i0 + 8;

    for (int c = 0; c < ntl; c++) {
        const uint32_t B0 = sb + 2 * ATILE_B + (c & 1) * (4 * ATILE_B);
        if (c + 1 < ntl)
            attn_ldkv(sb + 2 * ATILE_B + ((c + 1) & 1) * (4 * ATILE_B),
                      tid, (c + 1) * 64, Khp, Klp, Vhp, Vlp);
        const int kb = c * 64;

        // ---- S = Q K^T (3-pass split) ----
        float s[8][4];
        #pragma unroll
        for (int i = 0; i < 8; i++)
            #pragma unroll
            for (int j = 0; j < 4; j++) s[i][j] = 0.0f;

        #pragma unroll
        for (int kk = 0; kk < 4; kk++) {
            uint32_t kbh[8][2], kbl[8][2];
            #pragma unroll
            for (int p = 0; p < 4; p++) {
                const uint32_t rb = B0
                    + (p * 16 + (lane & 7) + ((lane >> 4) << 3)) * (ASTR * 2)
                    + (kk * 16 + ((lane >> 3) & 1) * 8) * 2;
                uint32_t r4[4];
                ldm4(r4, rb);
                kbh[p*2][0] = r4[0]; kbh[p*2][1] = r4[1];
                kbh[p*2+1][0] = r4[2]; kbh[p*2+1][1] = r4[3];
                ldm4(r4, rb + ATILE_B);
                kbl[p*2][0] = r4[0]; kbl[p*2][1] = r4[1];
                kbl[p*2+1][0] = r4[2]; kbl[p*2+1][1] = r4[3];
            }
            #pragma unroll
            for (int nt = 0; nt < 8; nt++) {
                mma16816(s[nt], qhi[kk], kbh[nt]);
                mma16816(s[nt], qlo[kk], kbh[nt]);
                mma16816(s[nt], qhi[kk], kbl[nt]);
            }
        }

        // ---- scale + mask + online softmax ----
        const bool domask = (c >= qt);
        float tm0 = -1e30f, tm1 = -1e30f;
        #pragma unroll
        for (int nt = 0; nt < 8; nt++) {
            const int j0 = kb + nt * 8 + 2 * q4;
            const float a0 = (j0 == 0) ? 0.0f : am[bSq + j0 - 1];
            const float a1 = am[bSq + j0];                 // col j0+1
            float v0 = fmaf(s[nt][0], 0.125f, a0);
            float v1 = fmaf(s[nt][1], 0.125f, a1);
            float v2 = fmaf(s[nt][2], 0.125f, a0);
            float v3 = fmaf(s[nt][3], 0.125f, a1);
            if (domask) {
                if (j0     > i0 + 1) v0 = -10000.0f + a0;
                if (j0 + 1 > i0 + 1) v1 = -10000.0f + a1;
                if (j0     > i1 + 1) v2 = -10000.0f + a0;
                if (j0 + 1 > i1 + 1) v3 = -10000.0f + a1;
            }
            s[nt][0] = v0; s[nt][1] = v1; s[nt][2] = v2; s[nt][3] = v3;
            tm0 = fmaxf(tm0, fmaxf(v0, v1));
            tm1 = fmaxf(tm1, fmaxf(v2, v3));
        }
        tm0 = fmaxf(tm0, __shfl_xor_sync(0xffffffffu, tm0, 1, 32));
        tm0 = fmaxf(tm0, __shfl_xor_sync(0xffffffffu, tm0, 2, 32));
        tm1 = fmaxf(tm1, __shfl_xor_sync(0xffffffffu, tm1, 1, 32));
        tm1 = fmaxf(tm1, __shfl_xor_sync(0xffffffffu, tm1, 2, 32));

        const float nm0 = fmaxf(m0, tm0), nm1 = fmaxf(m1, tm1);
        const float cor0 = fexp(m0 - nm0), cor1 = fexp(m1 - nm1);
        m0 = nm0; m1 = nm1;

        float rs0 = 0.0f, rs1 = 0.0f;
        #pragma unroll
        for (int nt = 0; nt < 8; nt++) {
            s[nt][0] = fexp(s[nt][0] - m0);
            s[nt][1] = fexp(s[nt][1] - m0);
            s[nt][2] = fexp(s[nt][2] - m1);
            s[nt][3] = fexp(s[nt][3] - m1);
            rs0 += s[nt][0] + s[nt][1];
            rs1 += s[nt][2] + s[nt][3];
        }
        rs0 += __shfl_xor_sync(0xffffffffu, rs0, 1, 32);
        rs0 += __shfl_xor_sync(0xffffffffu, rs0, 2, 32);
        rs1 += __shfl_xor_sync(0xffffffffu, rs1, 1, 32);
        rs1 += __shfl_xor_sync(0xffffffffu, rs1, 2, 32);
        l0 = l0 * cor0 + rs0;
        l1 = l1 * cor1 + rs1;
        #pragma unroll
        for (int nt = 0; nt < 8; nt++) {
            o[nt][0] *= cor0; o[nt][1] *= cor0;
            o[nt][2] *= cor1; o[nt][3] *= cor1;
        }

        // ---- pack P into A fragments (hi/lo) ----
        uint32_t phi[4][4], plo[4][4];
        #pragma unroll
        for (int kk = 0; kk < 4; kk++) {
            split2(s[2*kk][0],   s[2*kk][1],   phi[kk][0], plo[kk][0]);
            split2(s[2*kk][2],   s[2*kk][3],   phi[kk][1], plo[kk][1]);
            split2(s[2*kk+1][0], s[2*kk+1][1], phi[kk][2], plo[kk][2]);
            split2(s[2*kk+1][2], s[2*kk+1][3], phi[kk][3], plo[kk][3]);
        }

        // ---- O += P V (3-pass split), V via ldmatrix.trans ----
        const uint32_t Vb = B0 + 2 * ATILE_B;
        #pragma unroll
        for (int kk = 0; kk < 4; kk++) {
            #pragma unroll
            for (int np = 0; np < 4; np++) {
                const uint32_t va = Vb + (kk * 16 + (lane & 15)) * (ASTR * 2)
                                       + (np * 16 + (lane >> 4) * 8) * 2;
                uint32_t r4[4];
                ldm4t(r4, va);                       // Vhi
                {
                    uint32_t b0[2] = { r4[0], r4[1] };
                    uint32_t b1[2] = { r4[2], r4[3] };
                    mma16816(o[np*2],   phi[kk], b0);
                    mma16816(o[np*2+1], phi[kk], b1);
                    mma16816(o[np*2],   plo[kk], b0);
                    mma16816(o[np*2+1], plo[kk], b1);
                }
                ldm4t(r4, va + ATILE_B);             // Vlo
                {
                    uint32_t b0[2] = { r4[0], r4[1] };
                    uint32_t b1[2] = { r4[2], r4[3] };
                    mma16816(o[np*2],   phi[kk], b0);
                    mma16816(o[np*2+1], phi[kk], b1);
                }
            }
        }

        if (c + 1 < ntl) { CP_WAIT0(); __syncthreads(); }
    }

    // ---- epilogue: normalize, split to bf16 hi/lo for the proj GEMM ----
    const float inv0 = 1.0f / l0, inv1 = 1.0f / l1;
    const int qg0 = i0, qg1 = i1;
    #pragma unroll
    for (int nt = 0; nt < 8; nt++) {
        const int d0 = nt * 8 + 2 * q4;
        if (qg0 < Sq) {
            uint32_t hu, lu;
            split2(o[nt][0] * inv0, o[nt][1] * inv0, hu, lu);
            const size_t off = ((size_t)(bSq + qg0)) * EMB + h * HD + d0;
            *(uint32_t*)&g_AOhi[off] = hu;
            *(uint32_t*)&g_AOlo[off] = lu;
        }
        if (qg1 < Sq) {
            uint32_t hu, lu;
            split2(o[nt][2] * inv1, o[nt][3] * inv1, hu, lu);
            const size_t off = ((size_t)(bSq + qg1)) * EMB + h * HD + d0;
            *(uint32_t*)&g_AOhi[off] = hu;
            *(uint32_t*)&g_AOlo[off] = lu;
        }
    }
}

// =====================================================================
// launch
// =====================================================================
extern "C" void kernel_launch(void* const* d_in, const int* in_sizes, int n_in,
                              void* d_out, int out_size)
{
    const float* word = (const float*)d_in[0];
    const float* img  = (const float*)d_in[1];
    const float* am   = (const float*)d_in[2];
    const float* caw  = (const float*)d_in[3];
    const float* cab  = (const float*)d_in[4];
    const float* cpw  = (const float*)d_in[5];
    const float* cpb  = (const float*)d_in[6];
    const float* ukw  = (const float*)d_in[7];
    const float* ukb  = (const float*)d_in[8];
    const float* uvw  = (const float*)d_in[9];
    const float* uvb  = (const float*)d_in[10];
    float* out = (float*)d_out;

    cudaFuncSetAttribute(attn_kernel,
                         cudaFuncAttributeMaxDynamicSharedMemorySize, ATTN_SMEM);
    cudaFuncSetAttribute(gemm_mma_kernel,
                         cudaFuncAttributeMaxDynamicSharedMemorySize, GSMEM);

    conva_kernel<<<MPAD * EMB / 4 / 256, 256>>>(word);
    wconv_kernel<<<dim3(96, 32), dim3(32, 8)>>>(caw, 3 * EMB, 0);
    wconv_kernel<<<dim3(32, 32), dim3(32, 8)>>>(cpw, EMB, 1);
    pad_ao_kernel<<<16, 256>>>();

    gemm_mma_kernel<<<dim3(24, 32), 256, GSMEM>>>(cab, out, 0);     // qkv
    imgkv_kernel<<<1024, 256>>>(img, ukw, ukb, uvw, uvb);
    attn_kernel<<<dim3(16, NH, Bq), 128, ATTN_SMEM>>>(am);
    gemm_mma_kernel<<<dim3(8, 32), 256, GSMEM>>>(cpb, out, 1);      // proj
}